// round 5
// baseline (speedup 1.0000x reference)
#include <cuda_runtime.h>
#include <math.h>
#include <float.h>

#define B_    512
#define T_    247
#define C_    64
#define NTF_  200
#define LPOOL 254
#define MROWS (B_*T_)      // 126464

typedef unsigned long long u64;

// ---------------- scratch ----------------
__device__ float g_pooled[B_*C_*LPOOL];
__device__ float g_xlstm [MROWS*C_];
__device__ float g_xproj [(size_t)MROWS*512];
__device__ float g_values[MROWS*128];
__device__ float g_hT    [2*B_*64];
__device__ float g_query [B_*128];
__device__ float g_E     [MROWS*128];
__device__ float g_score [MROWS*NTF_];
__device__ float g_ctx   [B_*NTF_*128];
__device__ float g_W1T [128*128];
__device__ float g_W2T [128*128];
__device__ float g_VT  [128*NTF_];
__device__ float g_WIHT[64*512];
__device__ float g_biasIH[512];
__device__ float g_c1wT[512*64];

__device__ __forceinline__ float sigf(float x){ return 1.f/(1.f+__expf(-x)); }

// ---- packed fp32x2 helpers (FFMA2) ----
__device__ __forceinline__ u64 ffma2(u64 a, u64 b, u64 c){
    u64 d;
    asm("fma.rn.f32x2 %0, %1, %2, %3;" : "=l"(d) : "l"(a), "l"(b), "l"(c));
    return d;
}
__device__ __forceinline__ u64 pack2(float x, float y){
    u64 d;
    asm("mov.b64 %0, {%1, %2};" : "=l"(d) : "f"(x), "f"(y));
    return d;
}
__device__ __forceinline__ float2 unpack2(u64 d){
    float2 f;
    asm("mov.b64 {%0, %1}, %2;" : "=f"(f.x), "=f"(f.y) : "l"(d));
    return f;
}

// ---------------- prep ----------------
__global__ void k_prep(const float* __restrict__ W1, const float* __restrict__ W2,
                       const float* __restrict__ V,
                       const float* __restrict__ wih_f, const float* __restrict__ wih_b,
                       const float* __restrict__ bih_f, const float* __restrict__ bhh_f,
                       const float* __restrict__ bih_b, const float* __restrict__ bhh_b,
                       const float* __restrict__ c1w)
{
    int idx = blockIdx.x*blockDim.x + threadIdx.x;
    if (idx < 16384){ int n = idx/128, k = idx%128; g_W1T[k*128+n] = W1[idx]; }
    if (idx < 16384){ int n = idx/128, k = idx%128; g_W2T[k*128+n] = W2[idx]; }
    if (idx < 128*NTF_){ int n = idx/128, k = idx%128; g_VT[k*NTF_+n] = V[idx]; }
    if (idx < 16384){ int g = idx/64, k = idx%64;
        g_WIHT[k*512 + g]       = wih_f[idx];
        g_WIHT[k*512 + 256 + g] = wih_b[idx]; }
    if (idx < 512){ g_biasIH[idx] = (idx < 256) ? (bih_f[idx] + bhh_f[idx])
                                                : (bih_b[idx-256] + bhh_b[idx-256]); }
    if (idx < 32768){ int c = idx/512, k = idx%512; g_c1wT[k*64+c] = c1w[idx]; }
}

// ---------------- conv0 + bn + relu + maxpool4 ----------------
__global__ void __launch_bounds__(256) k_conv0(
    const float* __restrict__ x, const float* __restrict__ w, const float* __restrict__ cb,
    const float* __restrict__ g, const float* __restrict__ bb,
    const float* __restrict__ mm, const float* __restrict__ vv)
{
    __shared__ float4 xs4[1024];
    int b = blockIdx.x, tid = threadIdx.x;
    const float4* in4 = (const float4*)(x + (size_t)b*4096);
    for (int i = tid; i < 1024; i += 256) xs4[i] = in4[i];

    int c = tid & 63;
    float4 wr[8];
    #pragma unroll
    for (int kk = 0; kk < 8; kk++)
        wr[kk] = make_float4(w[c*32 + 0*8 + kk], w[c*32 + 1*8 + kk],
                             w[c*32 + 2*8 + kk], w[c*32 + 3*8 + kk]);
    float scale = g[c] * rsqrtf(vv[c] + 1e-5f);
    float shift = bb[c] - mm[c]*scale;
    float cbc   = cb[c];
    __syncthreads();

    for (int idx = tid; idx < 64*LPOOL; idx += 256){
        int q = idx >> 6;
        float best = -FLT_MAX;
        #pragma unroll
        for (int dp = 0; dp < 4; dp++){
            int p = 4*q + dp;
            float acc = cbc;
            #pragma unroll
            for (int kk = 0; kk < 8; kk++){
                float4 xv = xs4[p+kk];
                acc += wr[kk].x*xv.x + wr[kk].y*xv.y + wr[kk].z*xv.z + wr[kk].w*xv.w;
            }
            best = fmaxf(best, acc*scale + shift);
        }
        g_pooled[(b*64 + c)*LPOOL + q] = fmaxf(best, 0.f);
    }
}

// ---------------- f32x2 compute on one 16-k chunk ----------------
__device__ __forceinline__ void gcomp(const float (&As)[16][132], const float (&Bs)[16][132],
                                      u64 (&acc)[8][4], int ty, int tx)
{
    #pragma unroll
    for (int k = 0; k < 16; k++){
        float4 a0 = *(const float4*)&As[k][ty*8];
        float4 a1 = *(const float4*)&As[k][ty*8+4];
        uint4 bq0 = *(const uint4*)&Bs[k][tx*8];
        uint4 bq1 = *(const uint4*)&Bs[k][tx*8+4];
        u64 b0 = ((u64)bq0.y << 32) | bq0.x;
        u64 b1 = ((u64)bq0.w << 32) | bq0.z;
        u64 b2 = ((u64)bq1.y << 32) | bq1.x;
        u64 b3 = ((u64)bq1.w << 32) | bq1.z;
        float av[8] = {a0.x,a0.y,a0.z,a0.w,a1.x,a1.y,a1.z,a1.w};
        #pragma unroll
        for (int i = 0; i < 8; i++){
            u64 ai = pack2(av[i], av[i]);
            acc[i][0] = ffma2(ai, b0, acc[i][0]);
            acc[i][1] = ffma2(ai, b1, acc[i][1]);
            acc[i][2] = ffma2(ai, b2, acc[i][2]);
            acc[i][3] = ffma2(ai, b3, acc[i][3]);
        }
    }
}

// ---------------- conv1 GEMM: M=126464, N=64, K=512 (pipelined) ----------------
__global__ void __launch_bounds__(256,2) k_conv1(
    const float* __restrict__ cb,
    const float* __restrict__ gg, const float* __restrict__ bb,
    const float* __restrict__ mm, const float* __restrict__ vv)
{
    __shared__ float As[2][16][132];
    __shared__ float Bs[2][16][68];
    int tid = threadIdx.x;
    int m0  = blockIdx.x*128;
    int ty = tid/16, tx = tid%16;
    u64 acc[8][2];
    #pragma unroll
    for (int i=0;i<8;i++){ acc[i][0]=0ull; acc[i][1]=0ull; }

    int bzl[8], tl[8];
    #pragma unroll
    for (int r = 0; r < 8; r++){
        int i = tid + 256*r;
        int gm = m0 + (i >> 4);
        bzl[r] = gm / T_;
        tl[r]  = gm - bzl[r]*T_;
    }

    float ra[8], rb[4];
    #pragma unroll
    for (int r = 0; r < 8; r++){
        int i = tid + 256*r; int kg = i & 15;
        ra[r] = g_pooled[(bzl[r]*64 + (kg>>3))*LPOOL + tl[r] + (kg&7)];
    }
    #pragma unroll
    for (int r = 0; r < 4; r++){
        int i = tid + 256*r;
        rb[r] = g_c1wT[(i>>6)*64 + (i&63)];
    }
    #pragma unroll
    for (int r = 0; r < 8; r++){ int i = tid + 256*r; As[0][i&15][i>>4] = ra[r]; }
    #pragma unroll
    for (int r = 0; r < 4; r++){ int i = tid + 256*r; Bs[0][i>>6][i&63] = rb[r]; }
    __syncthreads();

    for (int c = 0; c < 32; c++){
        if (c < 31){
            int k0 = (c+1)*16;
            #pragma unroll
            for (int r = 0; r < 8; r++){
                int i = tid + 256*r; int kg = k0 + (i & 15);
                ra[r] = g_pooled[(bzl[r]*64 + (kg>>3))*LPOOL + tl[r] + (kg&7)];
            }
            #pragma unroll
            for (int r = 0; r < 4; r++){
                int i = tid + 256*r;
                rb[r] = g_c1wT[(k0 + (i>>6))*64 + (i&63)];
            }
        }
        {
            const float (&A)[16][132] = As[c&1];
            const float (&Bv)[16][68] = Bs[c&1];
            #pragma unroll
            for (int k = 0; k < 16; k++){
                float4 a0 = *(const float4*)&A[k][ty*8];
                float4 a1 = *(const float4*)&A[k][ty*8+4];
                uint4 bq = *(const uint4*)&Bv[k][tx*4];
                u64 b0 = ((u64)bq.y << 32) | bq.x;
                u64 b1 = ((u64)bq.w << 32) | bq.z;
                float av[8] = {a0.x,a0.y,a0.z,a0.w,a1.x,a1.y,a1.z,a1.w};
                #pragma unroll
                for (int i = 0; i < 8; i++){
                    u64 ai = pack2(av[i], av[i]);
                    acc[i][0] = ffma2(ai, b0, acc[i][0]);
                    acc[i][1] = ffma2(ai, b1, acc[i][1]);
                }
            }
        }
        if (c < 31){
            int nb = (c+1)&1;
            #pragma unroll
            for (int r = 0; r < 8; r++){ int i = tid + 256*r; As[nb][i&15][i>>4] = ra[r]; }
            #pragma unroll
            for (int r = 0; r < 4; r++){ int i = tid + 256*r; Bs[nb][i>>6][i&63] = rb[r]; }
        }
        __syncthreads();
    }
    #pragma unroll
    for (int j2 = 0; j2 < 2; j2++){
        #pragma unroll
        for (int h = 0; h < 2; h++){
            int c = tx*4 + j2*2 + h;
            float scale = gg[c] * rsqrtf(vv[c] + 1e-5f);
            float shift = bb[c] + (cb[c] - mm[c])*scale;
            #pragma unroll
            for (int i = 0; i < 8; i++){
                int m = m0 + ty*8 + i;
                float2 f = unpack2(acc[i][j2]);
                float v = h ? f.y : f.x;
                g_xlstm[(size_t)m*64 + c] = fmaxf(v*scale + shift, 0.f);
            }
        }
    }
}

// ---------------- xproj GEMM: M=126464, N=512, K=64 (pipelined) ----------------
__global__ void __launch_bounds__(256,2) k_xproj()
{
    __shared__ float As[2][16][132];
    __shared__ float Bs[2][16][132];
    int tid = threadIdx.x;
    int n0 = blockIdx.x*128, m0 = blockIdx.y*128;
    int ty = tid/16, tx = tid%16;
    u64 acc[8][4];
    #pragma unroll
    for (int i=0;i<8;i++) for (int j=0;j<4;j++) acc[i][j]=0ull;

    float ra[8], rb[8];
    #pragma unroll
    for (int r = 0; r < 8; r++){
        int i = tid + 256*r;
        ra[r] = g_xlstm[(size_t)(m0+(i>>4))*64 + (i&15)];
        rb[r] = g_WIHT[(i>>7)*512 + n0 + (i&127)];
    }
    #pragma unroll
    for (int r = 0; r < 8; r++){
        int i = tid + 256*r;
        As[0][i&15][i>>4] = ra[r]; Bs[0][i>>7][i&127] = rb[r];
    }
    __syncthreads();

    #pragma unroll
    for (int c = 0; c < 4; c++){
        if (c < 3){
            int k0 = (c+1)*16;
            #pragma unroll
            for (int r = 0; r < 8; r++){
                int i = tid + 256*r;
                ra[r] = g_xlstm[(size_t)(m0+(i>>4))*64 + k0 + (i&15)];
                rb[r] = g_WIHT[(k0+(i>>7))*512 + n0 + (i&127)];
            }
        }
        gcomp(As[c&1], Bs[c&1], acc, ty, tx);
        if (c < 3){
            int nb = (c+1)&1;
            #pragma unroll
            for (int r = 0; r < 8; r++){
                int i = tid + 256*r;
                As[nb][i&15][i>>4] = ra[r]; Bs[nb][i>>7][i&127] = rb[r];
            }
        }
        __syncthreads();
    }
    #pragma unroll
    for (int i = 0; i < 8; i++){
        int m = m0 + ty*8 + i;
        #pragma unroll
        for (int j2 = 0; j2 < 4; j2++){
            float2 f = unpack2(acc[i][j2]);
            int n = n0 + tx*8 + j2*2;
            g_xproj[(size_t)m*512 + n]     = f.x + g_biasIH[n];
            g_xproj[(size_t)m*512 + n + 1] = f.y + g_biasIH[n+1];
        }
    }
}

// ---------------- LSTM recurrence (persistent, f32x2, 4 batches/block) ----------------
__global__ void __launch_bounds__(256) k_lstm(const float* __restrict__ whh_f,
                                              const float* __restrict__ whh_b)
{
    __shared__ float hs[64][4];
    __shared__ float g_sm[4][256];
    int dir = blockIdx.x >> 7;
    int b0  = (blockIdx.x & 127) * 4;
    int tid = threadIdx.x;
    const float* whh = dir ? whh_b : whh_f;

    float4 w4[16];
    #pragma unroll
    for (int j4 = 0; j4 < 16; j4++) w4[j4] = *(const float4*)&whh[tid*64 + j4*4];

    hs[tid>>2][tid&3] = 0.f;
    float c = 0.f, hlast = 0.f;

    int tt0 = dir ? 246 : 0;
    float xv[4];
    #pragma unroll
    for (int bi = 0; bi < 4; bi++)
        xv[bi] = g_xproj[((size_t)(b0+bi)*T_ + tt0)*512 + dir*256 + tid];
    __syncthreads();

    for (int s = 0; s < T_; s++){
        u64 acc0 = pack2(xv[0], xv[1]);
        u64 acc1 = pack2(xv[2], xv[3]);

        float xn[4];
        if (s < T_-1){
            int tt2 = dir ? (245 - s) : (s + 1);
            #pragma unroll
            for (int bi = 0; bi < 4; bi++)
                xn[bi] = g_xproj[((size_t)(b0+bi)*T_ + tt2)*512 + dir*256 + tid];
        }

        #pragma unroll
        for (int j4 = 0; j4 < 16; j4++){
            float4 w = w4[j4];
            const ulonglong2* hq = (const ulonglong2*)&hs[j4*4][0];
            ulonglong2 h0 = hq[0];
            ulonglong2 h1 = hq[1];
            ulonglong2 h2 = hq[2];
            ulonglong2 h3 = hq[3];
            u64 wx = pack2(w.x, w.x);
            u64 wy = pack2(w.y, w.y);
            u64 wz = pack2(w.z, w.z);
            u64 ww = pack2(w.w, w.w);
            acc0 = ffma2(wx, h0.x, acc0); acc1 = ffma2(wx, h0.y, acc1);
            acc0 = ffma2(wy, h1.x, acc0); acc1 = ffma2(wy, h1.y, acc1);
            acc0 = ffma2(wz, h2.x, acc0); acc1 = ffma2(wz, h2.y, acc1);
            acc0 = ffma2(ww, h3.x, acc0); acc1 = ffma2(ww, h3.y, acc1);
        }
        float2 f0 = unpack2(acc0), f1 = unpack2(acc1);
        g_sm[0][tid] = f0.x; g_sm[1][tid] = f0.y;
        g_sm[2][tid] = f1.x; g_sm[3][tid] = f1.y;
        __syncthreads();

        int tv = dir ? (246 - s) : s;
        {
            int bi = tid >> 6, j = tid & 63;
            float gi = sigf(g_sm[bi][j]);
            float gf = sigf(g_sm[bi][64+j]);
            float gc = tanhf(g_sm[bi][128+j]);
            float go = sigf(g_sm[bi][192+j]);
            c = gf*c + gi*gc;
            float h = go * tanhf(c);
            hlast = h;
            hs[j][bi] = h;
            g_values[((size_t)(b0+bi)*T_ + tv)*128 + dir*64 + j] = h;
        }
        __syncthreads();
        #pragma unroll
        for (int bi = 0; bi < 4; bi++) xv[bi] = xn[bi];
    }
    {
        int bi = tid >> 6, j = tid & 63;
        g_hT[dir*B_*64 + (b0+bi)*64 + j] = hlast;
    }
}

// ---------------- h_n build + query ----------------
__global__ void k_hnquery(const float* __restrict__ W2b)
{
    __shared__ float hn[128];
    int b = blockIdx.x, j = threadIdx.x;
    int half = j >> 6, jj = j & 63;
    float v;
    if (b < 256) v = g_hT[(2*b + half)*64 + jj];
    else         v = g_hT[B_*64 + (2*(b-256) + half)*64 + jj];
    hn[j] = v;
    __syncthreads();
    float acc = W2b[j];
    #pragma unroll 4
    for (int k = 0; k < 128; k++) acc += hn[k] * g_W2T[k*128 + j];
    g_query[b*128 + j] = acc;
}

// ---------------- keys GEMM + tanh: M=126464, N=128, K=128 (pipelined) ----------------
__global__ void __launch_bounds__(256,2) k_keys(const float* __restrict__ W1b)
{
    __shared__ float As[2][16][132];
    __shared__ float Bs[2][16][132];
    int tid = threadIdx.x;
    int m0 = blockIdx.x*128;
    int ty = tid/16, tx = tid%16;
    u64 acc[8][4];
    #pragma unroll
    for (int i=0;i<8;i++) for (int j=0;j<4;j++) acc[i][j]=0ull;

    float ra[8], rb[8];
    #pragma unroll
    for (int r = 0; r < 8; r++){
        int i = tid + 256*r;
        ra[r] = g_values[(size_t)(m0+(i>>4))*128 + (i&15)];
        rb[r] = g_W1T[(i>>7)*128 + (i&127)];
    }
    #pragma unroll
    for (int r = 0; r < 8; r++){
        int i = tid + 256*r;
        As[0][i&15][i>>4] = ra[r]; Bs[0][i>>7][i&127] = rb[r];
    }
    __syncthreads();

    #pragma unroll
    for (int c = 0; c < 8; c++){
        if (c < 7){
            int k0 = (c+1)*16;
            #pragma unroll
            for (int r = 0; r < 8; r++){
                int i = tid + 256*r;
                ra[r] = g_values[(size_t)(m0+(i>>4))*128 + k0 + (i&15)];
                rb[r] = g_W1T[(k0+(i>>7))*128 + (i&127)];
            }
        }
        gcomp(As[c&1], Bs[c&1], acc, ty, tx);
        if (c < 7){
            int nb = (c+1)&1;
            #pragma unroll
            for (int r = 0; r < 8; r++){
                int i = tid + 256*r;
                As[nb][i&15][i>>4] = ra[r]; Bs[nb][i>>7][i&127] = rb[r];
            }
        }
        __syncthreads();
    }
    #pragma unroll
    for (int i = 0; i < 8; i++){
        int m = m0 + ty*8 + i;
        int b = m / T_;
        #pragma unroll
        for (int j2 = 0; j2 < 4; j2++){
            float2 f = unpack2(acc[i][j2]);
            int n = tx*8 + j2*2;
            g_E[(size_t)m*128 + n]   = tanhf(f.x + W1b[n]   + g_query[b*128 + n]);
            g_E[(size_t)m*128 + n+1] = tanhf(f.y + W1b[n+1] + g_query[b*128 + n+1]);
        }
    }
}

// ---------------- score GEMM (batched): per b, M=247, N=200, K=128 (pipelined) ----------------
__global__ void __launch_bounds__(256,2) k_scoreK(const float* __restrict__ Vb)
{
    __shared__ float As[2][16][132];
    __shared__ float Bs[2][16][132];
    int tid = threadIdx.x;
    int n0 = blockIdx.x*128, m0 = blockIdx.y*128, b = blockIdx.z;
    int ty = tid/16, tx = tid%16;
    u64 acc[8][4];
    #pragma unroll
    for (int i=0;i<8;i++) for (int j=0;j<4;j++) acc[i][j]=0ull;

    float ra[8], rb[8];
    #pragma unroll
    for (int r = 0; r < 8; r++){
        int i = tid + 256*r;
        ra[r] = (m0+(i>>4) < T_) ? g_E[((size_t)b*T_ + m0+(i>>4))*128 + (i&15)] : 0.f;
        rb[r] = (n0+(i&127) < NTF_) ? g_VT[(i>>7)*NTF_ + n0 + (i&127)] : 0.f;
    }
    #pragma unroll
    for (int r = 0; r < 8; r++){
        int i = tid + 256*r;
        As[0][i&15][i>>4] = ra[r]; Bs[0][i>>7][i&127] = rb[r];
    }
    __syncthreads();

    #pragma unroll
    for (int c = 0; c < 8; c++){
        if (c < 7){
            int k0 = (c+1)*16;
            #pragma unroll
            for (int r = 0; r < 8; r++){
                int i = tid + 256*r;
                ra[r] = (m0+(i>>4) < T_) ? g_E[((size_t)b*T_ + m0+(i>>4))*128 + k0 + (i&15)] : 0.f;
                rb[r] = (n0+(i&127) < NTF_) ? g_VT[(k0+(i>>7))*NTF_ + n0 + (i&127)] : 0.f;
            }
        }
        gcomp(As[c&1], Bs[c&1], acc, ty, tx);
        if (c < 7){
            int nb = (c+1)&1;
            #pragma unroll
            for (int r = 0; r < 8; r++){
                int i = tid + 256*r;
                As[nb][i&15][i>>4] = ra[r]; Bs[nb][i>>7][i&127] = rb[r];
            }
        }
        __syncthreads();
    }
    #pragma unroll
    for (int i = 0; i < 8; i++){
        int m = m0 + ty*8 + i;
        if (m >= T_) continue;
        #pragma unroll
        for (int j2 = 0; j2 < 4; j2++){
            float2 f = unpack2(acc[i][j2]);
            int n = n0 + tx*8 + j2*2;
            if (n < NTF_)
                g_score[((size_t)b*T_ + m)*NTF_ + n] = f.x + Vb[n];
            if (n+1 < NTF_)
                g_score[((size_t)b*T_ + m)*NTF_ + n+1] = f.y + Vb[n+1];
        }
    }
}

// ---------------- softmax over time ----------------
__global__ void k_softmax()
{
    int b = blockIdx.x, k = threadIdx.x;
    if (k >= NTF_) return;
    float* base = g_score + (size_t)b*T_*NTF_ + k;
    float m = -FLT_MAX, s = 0.f;
    for (int t = 0; t < T_; t++){
        float x = base[t*NTF_];
        if (x > m){ s = s*__expf(m - x) + 1.f; m = x; }
        else s += __expf(x - m);
    }
    float inv = 1.f / s;
    for (int t = 0; t < T_; t++){
        float x = base[t*NTF_];
        base[t*NTF_] = __expf(x - m) * inv;
    }
}

// ---------------- context GEMM (batched): per b, M=200, N=128, K=247 (pipelined) ----------------
__global__ void __launch_bounds__(256,2) k_context()
{
    __shared__ float As[2][16][132];
    __shared__ float Bs[2][16][132];
    int tid = threadIdx.x;
    int m0 = blockIdx.x*128, b = blockIdx.y;
    int ty = tid/16, tx = tid%16;
    u64 acc[8][4];
    #pragma unroll
    for (int i=0;i<8;i++) for (int j=0;j<4;j++) acc[i][j]=0ull;

    float ra[8], rb[8];
    #pragma unroll
    for (int r = 0; r < 8; r++){
        int i = tid + 256*r;
        int kA = i >> 7, mA = i & 127;
        ra[r] = (mA + m0 < NTF_) ? g_score[((size_t)b*T_ + kA)*NTF_ + m0 + mA] : 0.f;
        rb[r] = g_values[((size_t)b*T_ + (i>>7))*128 + (i&127)];
    }
    #pragma unroll
    for (int r = 0; r < 8; r++){
        int i = tid + 256*r;
        As[0][i>>7][i&127] = ra[r]; Bs[0][i>>7][i&127] = rb[r];
    }
    __syncthreads();

    for (int c = 0; c < 16; c++){
        if (c < 15){
            int kt0 = (c+1)*16;
            #pragma unroll
            for (int r = 0; r < 8; r++){
                int i = tid + 256*r;
                int kA = kt0 + (i >> 7), mA = i & 127;
                ra[r] = (kA < T_ && mA + m0 < NTF_)
                      ? g_score[((size_t)b*T_ + kA)*NTF_ + m0 + mA] : 0.f;
                rb[r] = (kA < T_)
                      ? g_values[((size_t)b*T_ + kA)*128 + (i&127)] : 0.f;
            }
        }
        gcomp(As[c&1], Bs[c&1], acc, ty, tx);
        if (c < 15){
            int nb = (c+1)&1;
            #pragma unroll
            for (int r = 0; r < 8; r++){
                int i = tid + 256*r;
                As[nb][i>>7][i&127] = ra[r]; Bs[nb][i>>7][i&127] = rb[r];
            }
        }
        __syncthreads();
    }
    #pragma unroll
    for (int i = 0; i < 8; i++){
        int m = m0 + ty*8 + i;
        if (m >= NTF_) continue;
        #pragma unroll
        for (int j2 = 0; j2 < 4; j2++){
            float2 f = unpack2(acc[i][j2]);
            int n = tx*8 + j2*2;
            g_ctx[((size_t)b*NTF_ + m)*128 + n]   = f.x;
            g_ctx[((size_t)b*NTF_ + m)*128 + n+1] = f.y;
        }
    }
}

// ---------------- per-TF heads ----------------
__global__ void __launch_bounds__(256) k_heads(
    const float* __restrict__ fc1w, const float* __restrict__ fc1b,
    const float* __restrict__ fc2w, const float* __restrict__ fc2b,
    float* __restrict__ out)
{
    __shared__ float fw[128][65];
    __shared__ float cs[16][128];
    __shared__ float red[16][65];
    int tid = threadIdx.x;
    int b0 = blockIdx.x*16, k = blockIdx.y;

    for (int i = tid; i < 8192; i += 256){
        int o = i >> 7, d = i & 127;
        fw[d][o] = fc1w[(size_t)k*8192 + i];
    }
    for (int i = tid; i < 2048; i += 256){
        int bi = i >> 7, d = i & 127;
        cs[bi][d] = g_ctx[((size_t)(b0+bi)*NTF_ + k)*128 + d];
    }
    __syncthreads();

    int o = tid & 63;
    float f1b = fc1b[k*64 + o];
    float f2w = fc2w[k*64 + o];
    #pragma unroll
    for (int p = 0; p < 4; p++){
        int bi = (tid >> 6) + p*4;
        float acc = 0.f;
        #pragma unroll
        for (int d4 = 0; d4 < 32; d4++){
            float4 cv = *(const float4*)&cs[bi][d4*4];
            acc += fw[d4*4+0][o]*cv.x + fw[d4*4+1][o]*cv.y
                 + fw[d4*4+2][o]*cv.z + fw[d4*4+3][o]*cv.w;
        }
        float h1 = fmaxf(acc + f1b, 0.f);
        red[bi][o] = h1 * f2w;
    }
    __syncthreads();
    if (tid < 16){
        float s = fc2b[k];
        #pragma unroll 8
        for (int oo = 0; oo < 64; oo++) s += red[tid][oo];
        out[(size_t)(b0 + tid)*NTF_ + k] = s;
    }
}

// ---------------- launch ----------------
extern "C" void kernel_launch(void* const* d_in, const int* in_sizes, int n_in,
                              void* d_out, int out_size)
{
    const float* DNA    = (const float*)d_in[0];
    const float* c0w    = (const float*)d_in[1];
    const float* c0b    = (const float*)d_in[2];
    const float* bn0g   = (const float*)d_in[3];
    const float* bn0b   = (const float*)d_in[4];
    const float* bn0m   = (const float*)d_in[5];
    const float* bn0v   = (const float*)d_in[6];
    const float* c1w    = (const float*)d_in[7];
    const float* c1b    = (const float*)d_in[8];
    const float* bn1g   = (const float*)d_in[9];
    const float* bn1b   = (const float*)d_in[10];
    const float* bn1m   = (const float*)d_in[11];
    const float* bn1v   = (const float*)d_in[12];
    const float* wih_f  = (const float*)d_in[13];
    const float* whh_f  = (const float*)d_in[14];
    const float* bih_f  = (const float*)d_in[15];
    const float* bhh_f  = (const float*)d_in[16];
    const float* wih_b  = (const float*)d_in[17];
    const float* whh_b  = (const float*)d_in[18];
    const float* bih_b  = (const float*)d_in[19];
    const float* bhh_b  = (const float*)d_in[20];
    const float* W1w    = (const float*)d_in[21];
    const float* W1b    = (const float*)d_in[22];
    const float* W2w    = (const float*)d_in[23];
    const float* W2b    = (const float*)d_in[24];
    const float* Vw     = (const float*)d_in[25];
    const float* Vb     = (const float*)d_in[26];
    const float* fc1w   = (const float*)d_in[27];
    const float* fc1b   = (const float*)d_in[28];
    const float* fc2w   = (const float*)d_in[29];
    const float* fc2b   = (const float*)d_in[30];
    float* out = (float*)d_out;

    k_prep<<<512, 256>>>(W1w, W2w, Vw, wih_f, wih_b, bih_f, bhh_f, bih_b, bhh_b, c1w);
    k_conv0<<<512, 256>>>(DNA, c0w, c0b, bn0g, bn0b, bn0m, bn0v);
    k_conv1<<<988, 256>>>(c1b, bn1g, bn1b, bn1m, bn1v);
    k_xproj<<<dim3(4, 988), 256>>>();
    k_lstm<<<256, 256>>>(whh_f, whh_b);
    k_hnquery<<<512, 128>>>(W2b);
    k_keys<<<988, 256>>>(W1b);
    k_scoreK<<<dim3(2, 2, 512), 256>>>(Vb);
    k_softmax<<<512, 256>>>();
    k_context<<<dim3(2, 512), 256>>>();
    k_heads<<<dim3(32, 200), 256>>>(fc1w, fc1b, fc2w, fc2b, out);
}

// round 6
// speedup vs baseline: 1.2061x; 1.2061x over previous
#include <cuda_runtime.h>
#include <math.h>
#include <float.h>

#define B_    512
#define T_    247
#define C_    64
#define NTF_  200
#define LPOOL 254
#define MROWS (B_*T_)      // 126464

typedef unsigned long long u64;

// ---------------- scratch ----------------
__device__ float g_pooled[B_*C_*LPOOL];
__device__ float g_xlstm [MROWS*C_];
__device__ float g_xproj [(size_t)MROWS*512];
__device__ float g_values[MROWS*128];
__device__ float g_hT    [2*B_*64];
__device__ float g_query [B_*128];
__device__ float g_E     [MROWS*128];
__device__ float g_score [MROWS*NTF_];
__device__ float g_ctx   [B_*NTF_*128];
__device__ float g_W1T [128*128];
__device__ float g_W2T [128*128];
__device__ float g_VT  [128*NTF_];
__device__ float g_WIHT[64*512];
__device__ float g_biasIH[512];
__device__ float g_c1wT[512*64];

__device__ __forceinline__ float sigf(float x){ return 1.f/(1.f+__expf(-x)); }

// ---- packed fp32x2 helpers (FFMA2) ----
__device__ __forceinline__ u64 ffma2(u64 a, u64 b, u64 c){
    u64 d;
    asm("fma.rn.f32x2 %0, %1, %2, %3;" : "=l"(d) : "l"(a), "l"(b), "l"(c));
    return d;
}
__device__ __forceinline__ u64 pack2(float x, float y){
    u64 d;
    asm("mov.b64 %0, {%1, %2};" : "=l"(d) : "f"(x), "f"(y));
    return d;
}
__device__ __forceinline__ float2 unpack2(u64 d){
    float2 f;
    asm("mov.b64 {%0, %1}, %2;" : "=f"(f.x), "=f"(f.y) : "l"(d));
    return f;
}

// ---------------- prep ----------------
__global__ void k_prep(const float* __restrict__ W1, const float* __restrict__ W2,
                       const float* __restrict__ V,
                       const float* __restrict__ wih_f, const float* __restrict__ wih_b,
                       const float* __restrict__ bih_f, const float* __restrict__ bhh_f,
                       const float* __restrict__ bih_b, const float* __restrict__ bhh_b,
                       const float* __restrict__ c1w)
{
    int idx = blockIdx.x*blockDim.x + threadIdx.x;
    if (idx < 16384){ int n = idx/128, k = idx%128; g_W1T[k*128+n] = W1[idx]; }
    if (idx < 16384){ int n = idx/128, k = idx%128; g_W2T[k*128+n] = W2[idx]; }
    if (idx < 128*NTF_){ int n = idx/128, k = idx%128; g_VT[k*NTF_+n] = V[idx]; }
    if (idx < 16384){ int g = idx/64, k = idx%64;
        g_WIHT[k*512 + g]       = wih_f[idx];
        g_WIHT[k*512 + 256 + g] = wih_b[idx]; }
    if (idx < 512){ g_biasIH[idx] = (idx < 256) ? (bih_f[idx] + bhh_f[idx])
                                                : (bih_b[idx-256] + bhh_b[idx-256]); }
    if (idx < 32768){ int c = idx/512, k = idx%512; g_c1wT[k*64+c] = c1w[idx]; }
}

// ---------------- conv0 + bn + relu + maxpool4 ----------------
__global__ void __launch_bounds__(256) k_conv0(
    const float* __restrict__ x, const float* __restrict__ w, const float* __restrict__ cb,
    const float* __restrict__ g, const float* __restrict__ bb,
    const float* __restrict__ mm, const float* __restrict__ vv)
{
    __shared__ float4 xs4[1024];
    int b = blockIdx.x, tid = threadIdx.x;
    const float4* in4 = (const float4*)(x + (size_t)b*4096);
    for (int i = tid; i < 1024; i += 256) xs4[i] = in4[i];

    int c = tid & 63;
    float4 wr[8];
    #pragma unroll
    for (int kk = 0; kk < 8; kk++)
        wr[kk] = make_float4(w[c*32 + 0*8 + kk], w[c*32 + 1*8 + kk],
                             w[c*32 + 2*8 + kk], w[c*32 + 3*8 + kk]);
    float scale = g[c] * rsqrtf(vv[c] + 1e-5f);
    float shift = bb[c] - mm[c]*scale;
    float cbc   = cb[c];
    __syncthreads();

    for (int idx = tid; idx < 64*LPOOL; idx += 256){
        int q = idx >> 6;
        float best = -FLT_MAX;
        #pragma unroll
        for (int dp = 0; dp < 4; dp++){
            int p = 4*q + dp;
            float acc = cbc;
            #pragma unroll
            for (int kk = 0; kk < 8; kk++){
                float4 xv = xs4[p+kk];
                acc += wr[kk].x*xv.x + wr[kk].y*xv.y + wr[kk].z*xv.z + wr[kk].w*xv.w;
            }
            best = fmaxf(best, acc*scale + shift);
        }
        g_pooled[(b*64 + c)*LPOOL + q] = fmaxf(best, 0.f);
    }
}

// ---------------- f32x2 compute on one 16-k chunk (conflict-free B) ----------------
__device__ __forceinline__ void gcomp(const float (&As)[16][132], const u64 (&Bs)[16][4][20],
                                      u64 (&acc)[8][4], int ty, int tx)
{
    #pragma unroll
    for (int k = 0; k < 16; k++){
        float4 a0 = *(const float4*)&As[k][ty*8];
        float4 a1 = *(const float4*)&As[k][ty*8+4];
        u64 b0 = Bs[k][0][tx];
        u64 b1 = Bs[k][1][tx];
        u64 b2 = Bs[k][2][tx];
        u64 b3 = Bs[k][3][tx];
        float av[8] = {a0.x,a0.y,a0.z,a0.w,a1.x,a1.y,a1.z,a1.w};
        #pragma unroll
        for (int i = 0; i < 8; i++){
            u64 ai = pack2(av[i], av[i]);
            acc[i][0] = ffma2(ai, b0, acc[i][0]);
            acc[i][1] = ffma2(ai, b1, acc[i][1]);
            acc[i][2] = ffma2(ai, b2, acc[i][2]);
            acc[i][3] = ffma2(ai, b3, acc[i][3]);
        }
    }
}

// store one B value into the pair layout: column n (0..127), row k
__device__ __forceinline__ void bstore(u64 (&Bs)[16][4][20], int k, int n, float v){
    ((float*)&Bs[k][(n>>1)&3][n>>3])[n&1] = v;
}

// ---------------- conv1 GEMM: M=126464, N=64, K=512 (pipelined) ----------------
__global__ void __launch_bounds__(256,2) k_conv1(
    const float* __restrict__ cb,
    const float* __restrict__ gg, const float* __restrict__ bb,
    const float* __restrict__ mm, const float* __restrict__ vv)
{
    __shared__ float As[2][16][132];
    __shared__ u64  Bs[2][16][2][20];
    int tid = threadIdx.x;
    int m0  = blockIdx.x*128;
    int ty = tid/16, tx = tid%16;
    u64 acc[8][2];
    #pragma unroll
    for (int i=0;i<8;i++){ acc[i][0]=0ull; acc[i][1]=0ull; }

    int bzl[8], tl[8];
    #pragma unroll
    for (int r = 0; r < 8; r++){
        int i = tid + 256*r;
        int gm = m0 + (i >> 4);
        bzl[r] = gm / T_;
        tl[r]  = gm - bzl[r]*T_;
    }

    float ra[8], rb[4];
    #pragma unroll
    for (int r = 0; r < 8; r++){
        int i = tid + 256*r; int kg = i & 15;
        ra[r] = g_pooled[(bzl[r]*64 + (kg>>3))*LPOOL + tl[r] + (kg&7)];
    }
    #pragma unroll
    for (int r = 0; r < 4; r++){
        int i = tid + 256*r;
        rb[r] = g_c1wT[(i>>6)*64 + (i&63)];
    }
    #pragma unroll
    for (int r = 0; r < 8; r++){ int i = tid + 256*r; As[0][i&15][i>>4] = ra[r]; }
    #pragma unroll
    for (int r = 0; r < 4; r++){
        int i = tid + 256*r; int n = i & 63, k = i >> 6;
        ((float*)&Bs[0][k][(n>>1)&1][n>>2])[n&1] = rb[r];
    }
    __syncthreads();

    for (int c = 0; c < 32; c++){
        if (c < 31){
            int k0 = (c+1)*16;
            #pragma unroll
            for (int r = 0; r < 8; r++){
                int i = tid + 256*r; int kg = k0 + (i & 15);
                ra[r] = g_pooled[(bzl[r]*64 + (kg>>3))*LPOOL + tl[r] + (kg&7)];
            }
            #pragma unroll
            for (int r = 0; r < 4; r++){
                int i = tid + 256*r;
                rb[r] = g_c1wT[(k0 + (i>>6))*64 + (i&63)];
            }
        }
        {
            const float (&A)[16][132] = As[c&1];
            const u64 (&Bv)[16][2][20] = Bs[c&1];
            #pragma unroll
            for (int k = 0; k < 16; k++){
                float4 a0 = *(const float4*)&A[k][ty*8];
                float4 a1 = *(const float4*)&A[k][ty*8+4];
                u64 b0 = Bv[k][0][tx];
                u64 b1 = Bv[k][1][tx];
                float av[8] = {a0.x,a0.y,a0.z,a0.w,a1.x,a1.y,a1.z,a1.w};
                #pragma unroll
                for (int i = 0; i < 8; i++){
                    u64 ai = pack2(av[i], av[i]);
                    acc[i][0] = ffma2(ai, b0, acc[i][0]);
                    acc[i][1] = ffma2(ai, b1, acc[i][1]);
                }
            }
        }
        if (c < 31){
            int nb = (c+1)&1;
            #pragma unroll
            for (int r = 0; r < 8; r++){ int i = tid + 256*r; As[nb][i&15][i>>4] = ra[r]; }
            #pragma unroll
            for (int r = 0; r < 4; r++){
                int i = tid + 256*r; int n = i & 63, k = i >> 6;
                ((float*)&Bs[nb][k][(n>>1)&1][n>>2])[n&1] = rb[r];
            }
        }
        __syncthreads();
    }
    #pragma unroll
    for (int j2 = 0; j2 < 2; j2++){
        #pragma unroll
        for (int h = 0; h < 2; h++){
            int c = tx*4 + j2*2 + h;
            float scale = gg[c] * rsqrtf(vv[c] + 1e-5f);
            float shift = bb[c] + (cb[c] - mm[c])*scale;
            #pragma unroll
            for (int i = 0; i < 8; i++){
                int m = m0 + ty*8 + i;
                float2 f = unpack2(acc[i][j2]);
                float v = h ? f.y : f.x;
                g_xlstm[(size_t)m*64 + c] = fmaxf(v*scale + shift, 0.f);
            }
        }
    }
}

// ---------------- xproj GEMM: M=126464, N=512, K=64 (pipelined) ----------------
__global__ void __launch_bounds__(256,2) k_xproj()
{
    __shared__ float As[2][16][132];
    __shared__ u64  Bs[2][16][4][20];
    int tid = threadIdx.x;
    int n0 = blockIdx.x*128, m0 = blockIdx.y*128;
    int ty = tid/16, tx = tid%16;
    u64 acc[8][4];
    #pragma unroll
    for (int i=0;i<8;i++) for (int j=0;j<4;j++) acc[i][j]=0ull;

    float ra[8], rb[8];
    #pragma unroll
    for (int r = 0; r < 8; r++){
        int i = tid + 256*r;
        ra[r] = g_xlstm[(size_t)(m0+(i>>4))*64 + (i&15)];
        rb[r] = g_WIHT[(i>>7)*512 + n0 + (i&127)];
    }
    #pragma unroll
    for (int r = 0; r < 8; r++){
        int i = tid + 256*r;
        As[0][i&15][i>>4] = ra[r];
        bstore(Bs[0], i>>7, i&127, rb[r]);
    }
    __syncthreads();

    #pragma unroll
    for (int c = 0; c < 4; c++){
        if (c < 3){
            int k0 = (c+1)*16;
            #pragma unroll
            for (int r = 0; r < 8; r++){
                int i = tid + 256*r;
                ra[r] = g_xlstm[(size_t)(m0+(i>>4))*64 + k0 + (i&15)];
                rb[r] = g_WIHT[(k0+(i>>7))*512 + n0 + (i&127)];
            }
        }
        gcomp(As[c&1], Bs[c&1], acc, ty, tx);
        if (c < 3){
            int nb = (c+1)&1;
            #pragma unroll
            for (int r = 0; r < 8; r++){
                int i = tid + 256*r;
                As[nb][i&15][i>>4] = ra[r];
                bstore(Bs[nb], i>>7, i&127, rb[r]);
            }
        }
        __syncthreads();
    }
    #pragma unroll
    for (int i = 0; i < 8; i++){
        int m = m0 + ty*8 + i;
        #pragma unroll
        for (int j2 = 0; j2 < 4; j2++){
            float2 f = unpack2(acc[i][j2]);
            int n = n0 + tx*8 + j2*2;
            g_xproj[(size_t)m*512 + n]     = f.x + g_biasIH[n];
            g_xproj[(size_t)m*512 + n + 1] = f.y + g_biasIH[n+1];
        }
    }
}

// ---------------- LSTM recurrence (persistent, f32x2, 4 batches/block) ----------------
__global__ void __launch_bounds__(256) k_lstm(const float* __restrict__ whh_f,
                                              const float* __restrict__ whh_b)
{
    __shared__ float hs[64][4];
    __shared__ float g_sm[4][256];
    int dir = blockIdx.x >> 7;
    int b0  = (blockIdx.x & 127) * 4;
    int tid = threadIdx.x;
    const float* whh = dir ? whh_b : whh_f;

    float4 w4[16];
    #pragma unroll
    for (int j4 = 0; j4 < 16; j4++) w4[j4] = *(const float4*)&whh[tid*64 + j4*4];

    hs[tid>>2][tid&3] = 0.f;
    float c = 0.f, hlast = 0.f;

    int tt0 = dir ? 246 : 0;
    float xv[4];
    #pragma unroll
    for (int bi = 0; bi < 4; bi++)
        xv[bi] = g_xproj[((size_t)(b0+bi)*T_ + tt0)*512 + dir*256 + tid];
    __syncthreads();

    for (int s = 0; s < T_; s++){
        u64 acc0 = pack2(xv[0], xv[1]);
        u64 acc1 = pack2(xv[2], xv[3]);

        float xn[4];
        if (s < T_-1){
            int tt2 = dir ? (245 - s) : (s + 1);
            #pragma unroll
            for (int bi = 0; bi < 4; bi++)
                xn[bi] = g_xproj[((size_t)(b0+bi)*T_ + tt2)*512 + dir*256 + tid];
        }

        #pragma unroll
        for (int j4 = 0; j4 < 16; j4++){
            float4 w = w4[j4];
            const ulonglong2* hq = (const ulonglong2*)&hs[j4*4][0];
            ulonglong2 h0 = hq[0];
            ulonglong2 h1 = hq[1];
            ulonglong2 h2 = hq[2];
            ulonglong2 h3 = hq[3];
            u64 wx = pack2(w.x, w.x);
            u64 wy = pack2(w.y, w.y);
            u64 wz = pack2(w.z, w.z);
            u64 ww = pack2(w.w, w.w);
            acc0 = ffma2(wx, h0.x, acc0); acc1 = ffma2(wx, h0.y, acc1);
            acc0 = ffma2(wy, h1.x, acc0); acc1 = ffma2(wy, h1.y, acc1);
            acc0 = ffma2(wz, h2.x, acc0); acc1 = ffma2(wz, h2.y, acc1);
            acc0 = ffma2(ww, h3.x, acc0); acc1 = ffma2(ww, h3.y, acc1);
        }
        float2 f0 = unpack2(acc0), f1 = unpack2(acc1);
        g_sm[0][tid] = f0.x; g_sm[1][tid] = f0.y;
        g_sm[2][tid] = f1.x; g_sm[3][tid] = f1.y;
        __syncthreads();

        int tv = dir ? (246 - s) : s;
        {
            int bi = tid >> 6, j = tid & 63;
            float gi = sigf(g_sm[bi][j]);
            float gf = sigf(g_sm[bi][64+j]);
            float gc = tanhf(g_sm[bi][128+j]);
            float go = sigf(g_sm[bi][192+j]);
            c = gf*c + gi*gc;
            float h = go * tanhf(c);
            hlast = h;
            hs[j][bi] = h;
            g_values[((size_t)(b0+bi)*T_ + tv)*128 + dir*64 + j] = h;
        }
        __syncthreads();
        #pragma unroll
        for (int bi = 0; bi < 4; bi++) xv[bi] = xn[bi];
    }
    {
        int bi = tid >> 6, j = tid & 63;
        g_hT[dir*B_*64 + (b0+bi)*64 + j] = hlast;
    }
}

// ---------------- h_n build + query ----------------
__global__ void k_hnquery(const float* __restrict__ W2b)
{
    __shared__ float hn[128];
    int b = blockIdx.x, j = threadIdx.x;
    int half = j >> 6, jj = j & 63;
    float v;
    if (b < 256) v = g_hT[(2*b + half)*64 + jj];
    else         v = g_hT[B_*64 + (2*(b-256) + half)*64 + jj];
    hn[j] = v;
    __syncthreads();
    float acc = W2b[j];
    #pragma unroll 4
    for (int k = 0; k < 128; k++) acc += hn[k] * g_W2T[k*128 + j];
    g_query[b*128 + j] = acc;
}

// ---------------- keys GEMM + tanh: M=126464, N=128, K=128 (pipelined) ----------------
__global__ void __launch_bounds__(256,2) k_keys(const float* __restrict__ W1b)
{
    __shared__ float As[2][16][132];
    __shared__ u64  Bs[2][16][4][20];
    int tid = threadIdx.x;
    int m0 = blockIdx.x*128;
    int ty = tid/16, tx = tid%16;
    u64 acc[8][4];
    #pragma unroll
    for (int i=0;i<8;i++) for (int j=0;j<4;j++) acc[i][j]=0ull;

    float ra[8], rb[8];
    #pragma unroll
    for (int r = 0; r < 8; r++){
        int i = tid + 256*r;
        ra[r] = g_values[(size_t)(m0+(i>>4))*128 + (i&15)];
        rb[r] = g_W1T[(i>>7)*128 + (i&127)];
    }
    #pragma unroll
    for (int r = 0; r < 8; r++){
        int i = tid + 256*r;
        As[0][i&15][i>>4] = ra[r];
        bstore(Bs[0], i>>7, i&127, rb[r]);
    }
    __syncthreads();

    #pragma unroll
    for (int c = 0; c < 8; c++){
        if (c < 7){
            int k0 = (c+1)*16;
            #pragma unroll
            for (int r = 0; r < 8; r++){
                int i = tid + 256*r;
                ra[r] = g_values[(size_t)(m0+(i>>4))*128 + k0 + (i&15)];
                rb[r] = g_W1T[(k0+(i>>7))*128 + (i&127)];
            }
        }
        gcomp(As[c&1], Bs[c&1], acc, ty, tx);
        if (c < 7){
            int nb = (c+1)&1;
            #pragma unroll
            for (int r = 0; r < 8; r++){
                int i = tid + 256*r;
                As[nb][i&15][i>>4] = ra[r];
                bstore(Bs[nb], i>>7, i&127, rb[r]);
            }
        }
        __syncthreads();
    }
    #pragma unroll
    for (int i = 0; i < 8; i++){
        int m = m0 + ty*8 + i;
        int b = m / T_;
        #pragma unroll
        for (int j2 = 0; j2 < 4; j2++){
            float2 f = unpack2(acc[i][j2]);
            int n = tx*8 + j2*2;
            g_E[(size_t)m*128 + n]   = tanhf(f.x + W1b[n]   + g_query[b*128 + n]);
            g_E[(size_t)m*128 + n+1] = tanhf(f.y + W1b[n+1] + g_query[b*128 + n+1]);
        }
    }
}

// ---------------- score GEMM (batched): per b, M=247, N=200, K=128 (pipelined) ----------------
__global__ void __launch_bounds__(256,2) k_scoreK(const float* __restrict__ Vb)
{
    __shared__ float As[2][16][132];
    __shared__ u64  Bs[2][16][4][20];
    int tid = threadIdx.x;
    int n0 = blockIdx.x*128, m0 = blockIdx.y*128, b = blockIdx.z;
    int ty = tid/16, tx = tid%16;
    u64 acc[8][4];
    #pragma unroll
    for (int i=0;i<8;i++) for (int j=0;j<4;j++) acc[i][j]=0ull;

    float ra[8], rb[8];
    #pragma unroll
    for (int r = 0; r < 8; r++){
        int i = tid + 256*r;
        ra[r] = (m0+(i>>4) < T_) ? g_E[((size_t)b*T_ + m0+(i>>4))*128 + (i&15)] : 0.f;
        rb[r] = (n0+(i&127) < NTF_) ? g_VT[(i>>7)*NTF_ + n0 + (i&127)] : 0.f;
    }
    #pragma unroll
    for (int r = 0; r < 8; r++){
        int i = tid + 256*r;
        As[0][i&15][i>>4] = ra[r];
        bstore(Bs[0], i>>7, i&127, rb[r]);
    }
    __syncthreads();

    #pragma unroll
    for (int c = 0; c < 8; c++){
        if (c < 7){
            int k0 = (c+1)*16;
            #pragma unroll
            for (int r = 0; r < 8; r++){
                int i = tid + 256*r;
                ra[r] = (m0+(i>>4) < T_) ? g_E[((size_t)b*T_ + m0+(i>>4))*128 + k0 + (i&15)] : 0.f;
                rb[r] = (n0+(i&127) < NTF_) ? g_VT[(k0+(i>>7))*NTF_ + n0 + (i&127)] : 0.f;
            }
        }
        gcomp(As[c&1], Bs[c&1], acc, ty, tx);
        if (c < 7){
            int nb = (c+1)&1;
            #pragma unroll
            for (int r = 0; r < 8; r++){
                int i = tid + 256*r;
                As[nb][i&15][i>>4] = ra[r];
                bstore(Bs[nb], i>>7, i&127, rb[r]);
            }
        }
        __syncthreads();
    }
    #pragma unroll
    for (int i = 0; i < 8; i++){
        int m = m0 + ty*8 + i;
        if (m >= T_) continue;
        #pragma unroll
        for (int j2 = 0; j2 < 4; j2++){
            float2 f = unpack2(acc[i][j2]);
            int n = n0 + tx*8 + j2*2;
            if (n < NTF_)
                g_score[((size_t)b*T_ + m)*NTF_ + n] = f.x + Vb[n];
            if (n+1 < NTF_)
                g_score[((size_t)b*T_ + m)*NTF_ + n+1] = f.y + Vb[n+1];
        }
    }
}

// ---------------- softmax over time ----------------
__global__ void k_softmax()
{
    int b = blockIdx.x, k = threadIdx.x;
    if (k >= NTF_) return;
    float* base = g_score + (size_t)b*T_*NTF_ + k;
    float m = -FLT_MAX, s = 0.f;
    for (int t = 0; t < T_; t++){
        float x = base[t*NTF_];
        if (x > m){ s = s*__expf(m - x) + 1.f; m = x; }
        else s += __expf(x - m);
    }
    float inv = 1.f / s;
    for (int t = 0; t < T_; t++){
        float x = base[t*NTF_];
        base[t*NTF_] = __expf(x - m) * inv;
    }
}

// ---------------- context GEMM (batched): per b, M=200, N=128, K=247 (pipelined) ----------------
__global__ void __launch_bounds__(256,2) k_context()
{
    __shared__ float As[2][16][132];
    __shared__ u64  Bs[2][16][4][20];
    int tid = threadIdx.x;
    int m0 = blockIdx.x*128, b = blockIdx.y;
    int ty = tid/16, tx = tid%16;
    u64 acc[8][4];
    #pragma unroll
    for (int i=0;i<8;i++) for (int j=0;j<4;j++) acc[i][j]=0ull;

    float ra[8], rb[8];
    #pragma unroll
    for (int r = 0; r < 8; r++){
        int i = tid + 256*r;
        int kA = i >> 7, mA = i & 127;
        ra[r] = (mA + m0 < NTF_) ? g_score[((size_t)b*T_ + kA)*NTF_ + m0 + mA] : 0.f;
        rb[r] = g_values[((size_t)b*T_ + kA)*128 + mA];
    }
    #pragma unroll
    for (int r = 0; r < 8; r++){
        int i = tid + 256*r;
        As[0][i>>7][i&127] = ra[r];
        bstore(Bs[0], i>>7, i&127, rb[r]);
    }
    __syncthreads();

    for (int c = 0; c < 16; c++){
        if (c < 15){
            int kt0 = (c+1)*16;
            #pragma unroll
            for (int r = 0; r < 8; r++){
                int i = tid + 256*r;
                int kA = kt0 + (i >> 7), mA = i & 127;
                ra[r] = (kA < T_ && mA + m0 < NTF_)
                      ? g_score[((size_t)b*T_ + kA)*NTF_ + m0 + mA] : 0.f;
                rb[r] = (kA < T_)
                      ? g_values[((size_t)b*T_ + kA)*128 + mA] : 0.f;
            }
        }
        gcomp(As[c&1], Bs[c&1], acc, ty, tx);
        if (c < 15){
            int nb = (c+1)&1;
            #pragma unroll
            for (int r = 0; r < 8; r++){
                int i = tid + 256*r;
                As[nb][i>>7][i&127] = ra[r];
                bstore(Bs[nb], i>>7, i&127, rb[r]);
            }
        }
        __syncthreads();
    }
    #pragma unroll
    for (int i = 0; i < 8; i++){
        int m = m0 + ty*8 + i;
        if (m >= NTF_) continue;
        #pragma unroll
        for (int j2 = 0; j2 < 4; j2++){
            float2 f = unpack2(acc[i][j2]);
            int n = tx*8 + j2*2;
            g_ctx[((size_t)b*NTF_ + m)*128 + n]   = f.x;
            g_ctx[((size_t)b*NTF_ + m)*128 + n+1] = f.y;
        }
    }
}

// ---------------- per-TF heads ----------------
__global__ void __launch_bounds__(256) k_heads(
    const float* __restrict__ fc1w, const float* __restrict__ fc1b,
    const float* __restrict__ fc2w, const float* __restrict__ fc2b,
    float* __restrict__ out)
{
    __shared__ float fw[128][65];
    __shared__ float cs[16][128];
    __shared__ float red[16][65];
    int tid = threadIdx.x;
    int b0 = blockIdx.x*16, k = blockIdx.y;

    for (int i = tid; i < 8192; i += 256){
        int o = i >> 7, d = i & 127;
        fw[d][o] = fc1w[(size_t)k*8192 + i];
    }
    for (int i = tid; i < 2048; i += 256){
        int bi = i >> 7, d = i & 127;
        cs[bi][d] = g_ctx[((size_t)(b0+bi)*NTF_ + k)*128 + d];
    }
    __syncthreads();

    int o = tid & 63;
    float f1b = fc1b[k*64 + o];
    float f2w = fc2w[k*64 + o];
    #pragma unroll
    for (int p = 0; p < 4; p++){
        int bi = (tid >> 6) + p*4;
        float acc = 0.f;
        #pragma unroll
        for (int d4 = 0; d4 < 32; d4++){
            float4 cv = *(const float4*)&cs[bi][d4*4];
            acc += fw[d4*4+0][o]*cv.x + fw[d4*4+1][o]*cv.y
                 + fw[d4*4+2][o]*cv.z + fw[d4*4+3][o]*cv.w;
        }
        float h1 = fmaxf(acc + f1b, 0.f);
        red[bi][o] = h1 * f2w;
    }
    __syncthreads();
    if (tid < 16){
        float s = fc2b[k];
        #pragma unroll 8
        for (int oo = 0; oo < 64; oo++) s += red[tid][oo];
        out[(size_t)(b0 + tid)*NTF_ + k] = s;
    }
}

// ---------------- launch ----------------
extern "C" void kernel_launch(void* const* d_in, const int* in_sizes, int n_in,
                              void* d_out, int out_size)
{
    const float* DNA    = (const float*)d_in[0];
    const float* c0w    = (const float*)d_in[1];
    const float* c0b    = (const float*)d_in[2];
    const float* bn0g   = (const float*)d_in[3];
    const float* bn0b   = (const float*)d_in[4];
    const float* bn0m   = (const float*)d_in[5];
    const float* bn0v   = (const float*)d_in[6];
    const float* c1w    = (const float*)d_in[7];
    const float* c1b    = (const float*)d_in[8];
    const float* bn1g   = (const float*)d_in[9];
    const float* bn1b   = (const float*)d_in[10];
    const float* bn1m   = (const float*)d_in[11];
    const float* bn1v   = (const float*)d_in[12];
    const float* wih_f  = (const float*)d_in[13];
    const float* whh_f  = (const float*)d_in[14];
    const float* bih_f  = (const float*)d_in[15];
    const float* bhh_f  = (const float*)d_in[16];
    const float* wih_b  = (const float*)d_in[17];
    const float* whh_b  = (const float*)d_in[18];
    const float* bih_b  = (const float*)d_in[19];
    const float* bhh_b  = (const float*)d_in[20];
    const float* W1w    = (const float*)d_in[21];
    const float* W1b    = (const float*)d_in[22];
    const float* W2w    = (const float*)d_in[23];
    const float* W2b    = (const float*)d_in[24];
    const float* Vw     = (const float*)d_in[25];
    const float* Vb     = (const float*)d_in[26];
    const float* fc1w   = (const float*)d_in[27];
    const float* fc1b   = (const float*)d_in[28];
    const float* fc2w   = (const float*)d_in[29];
    const float* fc2b   = (const float*)d_in[30];
    float* out = (float*)d_out;

    k_prep<<<512, 256>>>(W1w, W2w, Vw, wih_f, wih_b, bih_f, bhh_f, bih_b, bhh_b, c1w);
    k_conv0<<<512, 256>>>(DNA, c0w, c0b, bn0g, bn0b, bn0m, bn0v);
    k_conv1<<<988, 256>>>(c1b, bn1g, bn1b, bn1m, bn1v);
    k_xproj<<<dim3(4, 988), 256>>>();
    k_lstm<<<256, 256>>>(whh_f, whh_b);
    k_hnquery<<<512, 128>>>(W2b);
    k_keys<<<988, 256>>>(W1b);
    k_scoreK<<<dim3(2, 2, 512), 256>>>(Vb);
    k_softmax<<<512, 256>>>();
    k_context<<<dim3(2, 512), 256>>>();
    k_heads<<<dim3(32, 200), 256>>>(fc1w, fc1b, fc2w, fc2b, out);
}